// round 14
// baseline (speedup 1.0000x reference)
#include <cuda_runtime.h>
#include <cuda_fp16.h>
#include <cstdint>

// OnlineHadamard round 14: r10 VERBATIM (layouts, mappings, mix) with one change:
// the 4 butterfly chains for the next row are interleaved between kt-segments of
// the GEMM (after kt2/kt5/kt8/kt10), and the epilogue STGs go last before the
// barrier. Pure instruction-scheduling change to hide the shfl-chain latency.

#define KDIM 172
#define MDIM 64
#define NROW 11008
#define NT 384

#define ASTR 368
#define BSTR 144
#define A_BYTES (192 * ASTR)
#define B_BYTES (176 * BSTR)
#define OFF_B0  (A_BYTES)
#define OFF_B1  (A_BYTES + B_BYTES)
#define SMEM_DYN (A_BYTES + 2 * B_BYTES)   // 121344
#define NQUAD 43

__device__ __forceinline__ uint32_t smem_u32(const void* p) {
    uint32_t a;
    asm("{ .reg .u64 t; cvta.to.shared.u64 t, %1; cvt.u32.u64 %0, t; }" : "=r"(a) : "l"(p));
    return a;
}
__device__ __forceinline__ uint32_t h2_u32(__half2 h) {
    uint32_t u;
    *(__half2*)&u = h;
    return u;
}
__device__ __forceinline__ void ldsm_x4(uint32_t* r, uint32_t addr) {
    asm volatile("ldmatrix.sync.aligned.m8n8.x4.shared.b16 {%0,%1,%2,%3}, [%4];"
                 : "=r"(r[0]), "=r"(r[1]), "=r"(r[2]), "=r"(r[3]) : "r"(addr));
}
__device__ __forceinline__ void ldsm_x4t(uint32_t* r, uint32_t addr) {
    asm volatile("ldmatrix.sync.aligned.m8n8.x4.trans.shared.b16 {%0,%1,%2,%3}, [%4];"
                 : "=r"(r[0]), "=r"(r[1]), "=r"(r[2]), "=r"(r[3]) : "r"(addr));
}
__device__ __forceinline__ void mma_f16(float* c, const uint32_t* a, uint32_t b0, uint32_t b1) {
    asm volatile("mma.sync.aligned.m16n8k16.row.col.f32.f16.f16.f32 "
                 "{%0,%1,%2,%3}, {%4,%5,%6,%7}, {%8,%9}, {%0,%1,%2,%3};"
                 : "+f"(c[0]), "+f"(c[1]), "+f"(c[2]), "+f"(c[3])
                 : "r"(a[0]), "r"(a[1]), "r"(a[2]), "r"(a[3]), "r"(b0), "r"(b1));
}

// r10 butterfly verbatim: 8 elems/thread, m = {4tg..4tg+3, 32+4tg..32+4tg+3}.
__device__ __forceinline__ void bfly8_store(float4 lo, float4 hi, char* bbuf,
                                            int c, int tg, float scale) {
    float v[8] = {lo.x, lo.y, lo.z, lo.w, hi.x, hi.y, hi.z, hi.w};
    float t;
    #pragma unroll
    for (int i = 0; i < 4; i++) { t = v[i]; v[i] = t + v[i+4]; v[i+4] = t - v[i+4]; }
    #pragma unroll
    for (int g2 = 0; g2 < 8; g2 += 2) { t = v[g2]; v[g2] = t + v[g2+1]; v[g2+1] = t - v[g2+1]; }
    #pragma unroll
    for (int b = 0; b < 8; b += 4)
        #pragma unroll
        for (int i = 0; i < 2; i++) {
            t = v[b+i]; v[b+i] = t + v[b+i+2]; v[b+i+2] = t - v[b+i+2];
        }
    #pragma unroll
    for (int s = 1; s <= 4; s <<= 1) {
        bool up = (tg & s) != 0;
        #pragma unroll
        for (int i = 0; i < 8; i++) {
            float q = __shfl_xor_sync(0xffffffffu, v[i], s);
            v[i] = up ? (q - v[i]) : (v[i] + q);
        }
    }
    uint32_t h01 = h2_u32(__floats2half2_rn(v[0]*scale, v[1]*scale));
    uint32_t h23 = h2_u32(__floats2half2_rn(v[2]*scale, v[3]*scale));
    uint32_t h45 = h2_u32(__floats2half2_rn(v[4]*scale, v[5]*scale));
    uint32_t h67 = h2_u32(__floats2half2_rn(v[6]*scale, v[7]*scale));
    *(uint2*)(bbuf + c * BSTR + tg * 8)      = make_uint2(h01, h23);
    *(uint2*)(bbuf + c * BSTR + 64 + tg * 8) = make_uint2(h45, h67);
}

__global__ __launch_bounds__(NT, 1)
void onl_had_r14_kernel(const float* __restrict__ x,
                        const float* __restrict__ had,
                        float* __restrict__ out, int rows)
{
    extern __shared__ char sm[];
    const uint32_t sbase = smem_u32(sm);
    const int tid = threadIdx.x, lane = tid & 31, warp = tid >> 5;
    const int tg = lane & 7, g = lane >> 3;

    // ---- one-time: A = had (fp16), zero-padded ----
    for (int idx = tid; idx < 192 * 176; idx += NT) {
        int j = idx / 176, k = idx - j * 176;
        float v = (j < KDIM && k < KDIM) ? had[j * KDIM + k] : 0.0f;
        *(__half*)(sm + j * ASTR + 2 * k) = __float2half_rn(v);
    }
    for (int idx = tid; idx < 2 * 4 * 64; idx += NT) {
        int b = idx >> 8, r = (idx >> 6) & 3, m = idx & 63;
        char* p = sm + (b ? OFF_B1 : OFF_B0) + (172 + r) * BSTR;
        *(__half*)(p + 2 * m) = __float2half_rn(0.0f);
    }
    __syncthreads();

    const float scale = rsqrtf((float)NROW);
    const int stride = gridDim.x;

    // ---- warp tile: wj 0..5 (32 j), wm 0..1 (32 m) ----
    const int wj = warp >> 1, wm = warp & 1;
    uint32_t a_frag[2][11][4];
    #pragma unroll
    for (int jt2 = 0; jt2 < 2; jt2++) {
        uint32_t a_addr = sbase
            + (uint32_t)((wj * 32 + jt2 * 16) + (lane & 7) + ((lane >> 3) & 1) * 8) * ASTR
            + (uint32_t)((lane >> 4) * 16);
        #pragma unroll
        for (int kt = 0; kt < 11; kt++)
            ldsm_x4(a_frag[jt2][kt], a_addr + kt * 32);
    }

    uint32_t b_lane_off = (uint32_t)((lane & 15) * BSTR + (lane >> 4) * 16 + wm * 64);
    const int eq = lane & 3, er = lane >> 2;
    const uint32_t xoff = (uint32_t)(g * 64 + tg * 4);

    int row0 = blockIdx.x;
    if (row0 < rows) {
        const float* xr = x + (size_t)row0 * NROW;
        #pragma unroll
        for (int p = 0; p < 4; p++) {
            int q = warp + 12 * p;
            if (q < NQUAD) {
                const float* b = xr + q * 256 + xoff;
                bfly8_store(*(const float4*)b, *(const float4*)(b + 32),
                            sm + OFF_B0, 4 * q + g, tg, scale);
            }
        }
    }
    __syncthreads();

    int buf = 0;
    for (int row = row0; row < rows; row += stride) {
        const int nxt = row + stride;
        const bool have_nxt = nxt < rows;
        char* bnext = sm + (buf ? OFF_B0 : OFF_B1);

        // -- prefetch next row's quads --
        float4 pfl[4], pfh[4];
        if (have_nxt) {
            const float* xn = x + (size_t)nxt * NROW;
            #pragma unroll
            for (int p = 0; p < 4; p++) {
                int q = warp + 12 * p;
                if (q < NQUAD) {
                    const float* b = xn + q * 256 + xoff;
                    pfl[p] = *(const float4*)b;
                    pfh[p] = *(const float4*)(b + 32);
                }
            }
        }

        // -------- GEMM row i with butterfly chains interleaved --------
        uint32_t bbase = sbase + (buf ? OFF_B1 : OFF_B0) + b_lane_off;
        float acc[2][4][4];
        #pragma unroll
        for (int jt2 = 0; jt2 < 2; jt2++)
            #pragma unroll
            for (int n = 0; n < 4; n++)
                acc[jt2][n][0] = acc[jt2][n][1] = acc[jt2][n][2] = acc[jt2][n][3] = 0.f;

        auto gemm_step = [&](int kt) {
            uint32_t bk = bbase + (uint32_t)(kt * 16 * BSTR);
            uint32_t b0[4], b1[4];
            ldsm_x4t(b0, bk);
            ldsm_x4t(b1, bk + 32);
            #pragma unroll
            for (int jt2 = 0; jt2 < 2; jt2++) {
                mma_f16(acc[jt2][0], a_frag[jt2][kt], b0[0], b0[1]);
                mma_f16(acc[jt2][1], a_frag[jt2][kt], b0[2], b0[3]);
                mma_f16(acc[jt2][2], a_frag[jt2][kt], b1[0], b1[1]);
                mma_f16(acc[jt2][3], a_frag[jt2][kt], b1[2], b1[3]);
            }
        };
        auto chain = [&](int p) {
            int q = warp + 12 * p;
            if (have_nxt && q < NQUAD)
                bfly8_store(pfl[p], pfh[p], bnext, 4 * q + g, tg, scale);
        };

        gemm_step(0); gemm_step(1); gemm_step(2);
        chain(0);
        gemm_step(3); gemm_step(4); gemm_step(5);
        chain(1);
        gemm_step(6); gemm_step(7); gemm_step(8);
        chain(2);
        gemm_step(9); gemm_step(10);
        chain(3);

        // -------- epilogue last: fire-and-forget STGs, then barrier --------
        {
            float* orow = out + (size_t)row * NROW + wm * 32 + eq * 2;
            #pragma unroll
            for (int jt2 = 0; jt2 < 2; jt2++) {
                int j1 = wj * 32 + jt2 * 16 + er;
                int j2 = j1 + 8;
                if (j1 < KDIM) {
                    float* o1 = orow + j1 * MDIM;
                    #pragma unroll
                    for (int n = 0; n < 4; n++)
                        *(float2*)(o1 + n * 8) = make_float2(acc[jt2][n][0], acc[jt2][n][1]);
                }
                if (j2 < KDIM) {
                    float* o2 = orow + j2 * MDIM;
                    #pragma unroll
                    for (int n = 0; n < 4; n++)
                        *(float2*)(o2 + n * 8) = make_float2(acc[jt2][n][2], acc[jt2][n][3]);
                }
            }
        }
        buf ^= 1;
        __syncthreads();
    }
}

extern "C" void kernel_launch(void* const* d_in, const int* in_sizes, int n_in,
                              void* d_out, int out_size) {
    const float* x   = (const float*)d_in[0];
    const float* had = (const float*)d_in[1];
    float* out = (float*)d_out;
    int rows = in_sizes[0] / NROW;

    cudaFuncSetAttribute(onl_had_r14_kernel,
                         cudaFuncAttributeMaxDynamicSharedMemorySize, SMEM_DYN);
    int grid = rows < 152 ? rows : 152;
    onl_had_r14_kernel<<<grid, NT, SMEM_DYN>>>(x, had, out, rows);
}

// round 15
// speedup vs baseline: 1.1126x; 1.1126x over previous
#include <cuda_runtime.h>
#include <cuda_fp16.h>
#include <cstdint>

// OnlineHadamard round 15: r10 verbatim (layouts/mappings/order), with the row
// loop processing TWO rows per __syncthreads (4 B buffers). No other changes.

#define KDIM 172
#define MDIM 64
#define NROW 11008
#define NT 384

#define ASTR 368
#define BSTR 144
#define A_BYTES (192 * ASTR)              // 70656
#define B_BYTES (176 * BSTR)              // 25344
#define OFF_B(i) (A_BYTES + (i) * B_BYTES)
#define SMEM_DYN (A_BYTES + 4 * B_BYTES)  // 172032
#define NQUAD 43

__device__ __forceinline__ uint32_t smem_u32(const void* p) {
    uint32_t a;
    asm("{ .reg .u64 t; cvta.to.shared.u64 t, %1; cvt.u32.u64 %0, t; }" : "=r"(a) : "l"(p));
    return a;
}
__device__ __forceinline__ uint32_t h2_u32(__half2 h) {
    uint32_t u;
    *(__half2*)&u = h;
    return u;
}
__device__ __forceinline__ void ldsm_x4(uint32_t* r, uint32_t addr) {
    asm volatile("ldmatrix.sync.aligned.m8n8.x4.shared.b16 {%0,%1,%2,%3}, [%4];"
                 : "=r"(r[0]), "=r"(r[1]), "=r"(r[2]), "=r"(r[3]) : "r"(addr));
}
__device__ __forceinline__ void ldsm_x4t(uint32_t* r, uint32_t addr) {
    asm volatile("ldmatrix.sync.aligned.m8n8.x4.trans.shared.b16 {%0,%1,%2,%3}, [%4];"
                 : "=r"(r[0]), "=r"(r[1]), "=r"(r[2]), "=r"(r[3]) : "r"(addr));
}
__device__ __forceinline__ void mma_f16(float* c, const uint32_t* a, uint32_t b0, uint32_t b1) {
    asm volatile("mma.sync.aligned.m16n8k16.row.col.f32.f16.f16.f32 "
                 "{%0,%1,%2,%3}, {%4,%5,%6,%7}, {%8,%9}, {%0,%1,%2,%3};"
                 : "+f"(c[0]), "+f"(c[1]), "+f"(c[2]), "+f"(c[3])
                 : "r"(a[0]), "r"(a[1]), "r"(a[2]), "r"(a[3]), "r"(b0), "r"(b1));
}

// r10 butterfly verbatim: 8 elems/thread, m = {4tg..4tg+3, 32+4tg..32+4tg+3}.
__device__ __forceinline__ void bfly8_store(float4 lo, float4 hi, char* bbuf,
                                            int c, int tg, float scale) {
    float v[8] = {lo.x, lo.y, lo.z, lo.w, hi.x, hi.y, hi.z, hi.w};
    float t;
    #pragma unroll
    for (int i = 0; i < 4; i++) { t = v[i]; v[i] = t + v[i+4]; v[i+4] = t - v[i+4]; }
    #pragma unroll
    for (int g2 = 0; g2 < 8; g2 += 2) { t = v[g2]; v[g2] = t + v[g2+1]; v[g2+1] = t - v[g2+1]; }
    #pragma unroll
    for (int b = 0; b < 8; b += 4)
        #pragma unroll
        for (int i = 0; i < 2; i++) {
            t = v[b+i]; v[b+i] = t + v[b+i+2]; v[b+i+2] = t - v[b+i+2];
        }
    #pragma unroll
    for (int s = 1; s <= 4; s <<= 1) {
        bool up = (tg & s) != 0;
        #pragma unroll
        for (int i = 0; i < 8; i++) {
            float q = __shfl_xor_sync(0xffffffffu, v[i], s);
            v[i] = up ? (q - v[i]) : (v[i] + q);
        }
    }
    uint32_t h01 = h2_u32(__floats2half2_rn(v[0]*scale, v[1]*scale));
    uint32_t h23 = h2_u32(__floats2half2_rn(v[2]*scale, v[3]*scale));
    uint32_t h45 = h2_u32(__floats2half2_rn(v[4]*scale, v[5]*scale));
    uint32_t h67 = h2_u32(__floats2half2_rn(v[6]*scale, v[7]*scale));
    *(uint2*)(bbuf + c * BSTR + tg * 8)      = make_uint2(h01, h23);
    *(uint2*)(bbuf + c * BSTR + 64 + tg * 8) = make_uint2(h45, h67);
}

// One row's GEMM + epilogue, r10 inner loop verbatim. All a_frag indices
// compile-time (fully unrolled).
__device__ __forceinline__ void gemm_epi(const uint32_t a_frag[2][11][4],
                                         uint32_t bbase,
                                         float* __restrict__ out, int row,
                                         int wj, int wm, int eq, int er) {
    float acc[2][4][4];
    #pragma unroll
    for (int jt2 = 0; jt2 < 2; jt2++)
        #pragma unroll
        for (int n = 0; n < 4; n++)
            acc[jt2][n][0] = acc[jt2][n][1] = acc[jt2][n][2] = acc[jt2][n][3] = 0.f;

    #pragma unroll
    for (int kt = 0; kt < 11; kt++) {
        uint32_t bk = bbase + (uint32_t)(kt * 16 * BSTR);
        uint32_t b0[4], b1[4];
        ldsm_x4t(b0, bk);
        ldsm_x4t(b1, bk + 32);
        #pragma unroll
        for (int jt2 = 0; jt2 < 2; jt2++) {
            mma_f16(acc[jt2][0], a_frag[jt2][kt], b0[0], b0[1]);
            mma_f16(acc[jt2][1], a_frag[jt2][kt], b0[2], b0[3]);
            mma_f16(acc[jt2][2], a_frag[jt2][kt], b1[0], b1[1]);
            mma_f16(acc[jt2][3], a_frag[jt2][kt], b1[2], b1[3]);
        }
    }
    float* orow = out + (size_t)row * NROW + wm * 32 + eq * 2;
    #pragma unroll
    for (int jt2 = 0; jt2 < 2; jt2++) {
        int j1 = wj * 32 + jt2 * 16 + er;
        int j2 = j1 + 8;
        if (j1 < KDIM) {
            float* o1 = orow + j1 * MDIM;
            #pragma unroll
            for (int n = 0; n < 4; n++)
                *(float2*)(o1 + n * 8) = make_float2(acc[jt2][n][0], acc[jt2][n][1]);
        }
        if (j2 < KDIM) {
            float* o2 = orow + j2 * MDIM;
            #pragma unroll
            for (int n = 0; n < 4; n++)
                *(float2*)(o2 + n * 8) = make_float2(acc[jt2][n][2], acc[jt2][n][3]);
        }
    }
}

__global__ __launch_bounds__(NT, 1)
void onl_had_r15_kernel(const float* __restrict__ x,
                        const float* __restrict__ had,
                        float* __restrict__ out, int rows)
{
    extern __shared__ char sm[];
    const uint32_t sbase = smem_u32(sm);
    const int tid = threadIdx.x, lane = tid & 31, warp = tid >> 5;
    const int tg = lane & 7, g = lane >> 3;

    // ---- one-time: A = had (fp16), zero-padded ----
    for (int idx = tid; idx < 192 * 176; idx += NT) {
        int j = idx / 176, k = idx - j * 176;
        float v = (j < KDIM && k < KDIM) ? had[j * KDIM + k] : 0.0f;
        *(__half*)(sm + j * ASTR + 2 * k) = __float2half_rn(v);
    }
    // zero B pad rows 172..175 in all 4 buffers
    for (int idx = tid; idx < 4 * 4 * 64; idx += NT) {
        int b = idx >> 8, r = (idx >> 6) & 3, m = idx & 63;
        char* p = sm + OFF_B(b) + (172 + r) * BSTR;
        *(__half*)(p + 2 * m) = __float2half_rn(0.0f);
    }
    __syncthreads();

    const float scale = rsqrtf((float)NROW);
    const int s1 = gridDim.x, s2 = 2 * s1;

    // ---- warp tile (r10 verbatim) ----
    const int wj = warp >> 1, wm = warp & 1;
    uint32_t a_frag[2][11][4];
    #pragma unroll
    for (int jt2 = 0; jt2 < 2; jt2++) {
        uint32_t a_addr = sbase
            + (uint32_t)((wj * 32 + jt2 * 16) + (lane & 7) + ((lane >> 3) & 1) * 8) * ASTR
            + (uint32_t)((lane >> 4) * 16);
        #pragma unroll
        for (int kt = 0; kt < 11; kt++)
            ldsm_x4(a_frag[jt2][kt], a_addr + kt * 32);
    }

    const uint32_t b_lane_off = (uint32_t)((lane & 15) * BSTR + (lane >> 4) * 16 + wm * 64);
    const int eq = lane & 3, er = lane >> 2;
    const uint32_t xoff = (uint32_t)(g * 64 + tg * 4);

    // ---- prologue: rows row0, row0+s1 into buffers 0, 1 (r10 FHT path) ----
    int row0 = blockIdx.x;
    #pragma unroll 1
    for (int h = 0; h < 2; h++) {
        int r = row0 + h * s1;
        if (r < rows) {
            const float* xr = x + (size_t)r * NROW;
            char* bb = sm + OFF_B(h);
            #pragma unroll
            for (int p = 0; p < 4; p++) {
                int q = warp + 12 * p;
                if (q < NQUAD) {
                    const float* b = xr + q * 256 + xoff;
                    bfly8_store(*(const float4*)b, *(const float4*)(b + 32),
                                bb, 4 * q + g, tg, scale);
                }
            }
        }
    }
    __syncthreads();

    int pb = 0;
    for (int ra = row0; ra < rows; ra += s2) {
        const int rb = ra + s1, rc = ra + s2, rd = ra + 3 * s1;

        // ---- half 1: pf(rc) -> GEMM+epi(ra) -> bfly(rc) ----
        {
            float4 pfl[4], pfh[4];
            const bool hv = rc < rows;
            if (hv) {
                const float* xn = x + (size_t)rc * NROW;
                #pragma unroll
                for (int p = 0; p < 4; p++) {
                    int q = warp + 12 * p;
                    if (q < NQUAD) {
                        const float* b = xn + q * 256 + xoff;
                        pfl[p] = *(const float4*)b;
                        pfh[p] = *(const float4*)(b + 32);
                    }
                }
            }
            gemm_epi(a_frag, sbase + (uint32_t)OFF_B(pb) + b_lane_off,
                     out, ra, wj, wm, eq, er);
            if (hv) {
                char* bb = sm + OFF_B(pb ^ 2);
                #pragma unroll
                for (int p = 0; p < 4; p++) {
                    int q = warp + 12 * p;
                    if (q < NQUAD)
                        bfly8_store(pfl[p], pfh[p], bb, 4 * q + g, tg, scale);
                }
            }
        }

        // ---- half 2: pf(rd) -> GEMM+epi(rb) -> bfly(rd) ----
        if (rb < rows) {
            float4 pfl[4], pfh[4];
            const bool hv = rd < rows;
            if (hv) {
                const float* xn = x + (size_t)rd * NROW;
                #pragma unroll
                for (int p = 0; p < 4; p++) {
                    int q = warp + 12 * p;
                    if (q < NQUAD) {
                        const float* b = xn + q * 256 + xoff;
                        pfl[p] = *(const float4*)b;
                        pfh[p] = *(const float4*)(b + 32);
                    }
                }
            }
            gemm_epi(a_frag, sbase + (uint32_t)OFF_B(pb + 1) + b_lane_off,
                     out, rb, wj, wm, eq, er);
            if (hv) {
                char* bb = sm + OFF_B((pb ^ 2) + 1);
                #pragma unroll
                for (int p = 0; p < 4; p++) {
                    int q = warp + 12 * p;
                    if (q < NQUAD)
                        bfly8_store(pfl[p], pfh[p], bb, 4 * q + g, tg, scale);
                }
            }
        }

        pb ^= 2;
        __syncthreads();
    }
}

extern "C" void kernel_launch(void* const* d_in, const int* in_sizes, int n_in,
                              void* d_out, int out_size) {
    const float* x   = (const float*)d_in[0];
    const float* had = (const float*)d_in[1];
    float* out = (float*)d_out;
    int rows = in_sizes[0] / NROW;

    cudaFuncSetAttribute(onl_had_r15_kernel,
                         cudaFuncAttributeMaxDynamicSharedMemorySize, SMEM_DYN);
    int grid = rows < 152 ? rows : 152;
    onl_had_r15_kernel<<<grid, NT, SMEM_DYN>>>(x, had, out, rows);
}

// round 16
// speedup vs baseline: 1.6621x; 1.4939x over previous
#include <cuda_runtime.h>
#include <cuda_fp16.h>
#include <cstdint>

// OnlineHadamard round 16: r10 byte-identical, plus streaming cache hints:
// __ldcs on x prefetch (read-once), __stcs on out epilogue (write-once).

#define KDIM 172
#define MDIM 64
#define NROW 11008
#define NT 384

#define ASTR 368
#define BSTR 144
#define A_BYTES (192 * ASTR)
#define B_BYTES (176 * BSTR)
#define OFF_B0  (A_BYTES)
#define OFF_B1  (A_BYTES + B_BYTES)
#define SMEM_DYN (A_BYTES + 2 * B_BYTES)   // 121344
#define NQUAD 43

__device__ __forceinline__ uint32_t smem_u32(const void* p) {
    uint32_t a;
    asm("{ .reg .u64 t; cvta.to.shared.u64 t, %1; cvt.u32.u64 %0, t; }" : "=r"(a) : "l"(p));
    return a;
}
__device__ __forceinline__ uint32_t h2_u32(__half2 h) {
    uint32_t u;
    *(__half2*)&u = h;
    return u;
}
__device__ __forceinline__ void ldsm_x4(uint32_t* r, uint32_t addr) {
    asm volatile("ldmatrix.sync.aligned.m8n8.x4.shared.b16 {%0,%1,%2,%3}, [%4];"
                 : "=r"(r[0]), "=r"(r[1]), "=r"(r[2]), "=r"(r[3]) : "r"(addr));
}
__device__ __forceinline__ void ldsm_x4t(uint32_t* r, uint32_t addr) {
    asm volatile("ldmatrix.sync.aligned.m8n8.x4.trans.shared.b16 {%0,%1,%2,%3}, [%4];"
                 : "=r"(r[0]), "=r"(r[1]), "=r"(r[2]), "=r"(r[3]) : "r"(addr));
}
__device__ __forceinline__ void mma_f16(float* c, const uint32_t* a, uint32_t b0, uint32_t b1) {
    asm volatile("mma.sync.aligned.m16n8k16.row.col.f32.f16.f16.f32 "
                 "{%0,%1,%2,%3}, {%4,%5,%6,%7}, {%8,%9}, {%0,%1,%2,%3};"
                 : "+f"(c[0]), "+f"(c[1]), "+f"(c[2]), "+f"(c[3])
                 : "r"(a[0]), "r"(a[1]), "r"(a[2]), "r"(a[3]), "r"(b0), "r"(b1));
}

// r10 butterfly verbatim: 8 elems/thread, m = {4tg..4tg+3, 32+4tg..32+4tg+3}.
__device__ __forceinline__ void bfly8_store(float4 lo, float4 hi, char* bbuf,
                                            int c, int tg, float scale) {
    float v[8] = {lo.x, lo.y, lo.z, lo.w, hi.x, hi.y, hi.z, hi.w};
    float t;
    #pragma unroll
    for (int i = 0; i < 4; i++) { t = v[i]; v[i] = t + v[i+4]; v[i+4] = t - v[i+4]; }
    #pragma unroll
    for (int g2 = 0; g2 < 8; g2 += 2) { t = v[g2]; v[g2] = t + v[g2+1]; v[g2+1] = t - v[g2+1]; }
    #pragma unroll
    for (int b = 0; b < 8; b += 4)
        #pragma unroll
        for (int i = 0; i < 2; i++) {
            t = v[b+i]; v[b+i] = t + v[b+i+2]; v[b+i+2] = t - v[b+i+2];
        }
    #pragma unroll
    for (int s = 1; s <= 4; s <<= 1) {
        bool up = (tg & s) != 0;
        #pragma unroll
        for (int i = 0; i < 8; i++) {
            float q = __shfl_xor_sync(0xffffffffu, v[i], s);
            v[i] = up ? (q - v[i]) : (v[i] + q);
        }
    }
    uint32_t h01 = h2_u32(__floats2half2_rn(v[0]*scale, v[1]*scale));
    uint32_t h23 = h2_u32(__floats2half2_rn(v[2]*scale, v[3]*scale));
    uint32_t h45 = h2_u32(__floats2half2_rn(v[4]*scale, v[5]*scale));
    uint32_t h67 = h2_u32(__floats2half2_rn(v[6]*scale, v[7]*scale));
    *(uint2*)(bbuf + c * BSTR + tg * 8)      = make_uint2(h01, h23);
    *(uint2*)(bbuf + c * BSTR + 64 + tg * 8) = make_uint2(h45, h67);
}

__global__ __launch_bounds__(NT, 1)
void onl_had_r16_kernel(const float* __restrict__ x,
                        const float* __restrict__ had,
                        float* __restrict__ out, int rows)
{
    extern __shared__ char sm[];
    const uint32_t sbase = smem_u32(sm);
    const int tid = threadIdx.x, lane = tid & 31, warp = tid >> 5;
    const int tg = lane & 7, g = lane >> 3;

    // ---- one-time: A = had (fp16), zero-padded to 192x176 ----
    for (int idx = tid; idx < 192 * 176; idx += NT) {
        int j = idx / 176, k = idx - j * 176;
        float v = (j < KDIM && k < KDIM) ? had[j * KDIM + k] : 0.0f;
        *(__half*)(sm + j * ASTR + 2 * k) = __float2half_rn(v);
    }
    for (int idx = tid; idx < 2 * 4 * 64; idx += NT) {
        int b = idx >> 8, r = (idx >> 6) & 3, m = idx & 63;
        char* p = sm + (b ? OFF_B1 : OFF_B0) + (172 + r) * BSTR;
        *(__half*)(p + 2 * m) = __float2half_rn(0.0f);
    }
    __syncthreads();

    const float scale = rsqrtf((float)NROW);
    const int stride = gridDim.x;

    // ---- warp tile: wj 0..5 (32 j), wm 0..1 (32 m) ----
    const int wj = warp >> 1, wm = warp & 1;
    uint32_t a_frag[2][11][4];
    #pragma unroll
    for (int jt2 = 0; jt2 < 2; jt2++) {
        uint32_t a_addr = sbase
            + (uint32_t)((wj * 32 + jt2 * 16) + (lane & 7) + ((lane >> 3) & 1) * 8) * ASTR
            + (uint32_t)((lane >> 4) * 16);
        #pragma unroll
        for (int kt = 0; kt < 11; kt++)
            ldsm_x4(a_frag[jt2][kt], a_addr + kt * 32);
    }

    uint32_t b_lane_off = (uint32_t)((lane & 15) * BSTR + (lane >> 4) * 16 + wm * 64);
    const int eq = lane & 3, er = lane >> 2;
    const uint32_t xoff = (uint32_t)(g * 64 + tg * 4);

    int row0 = blockIdx.x;
    if (row0 < rows) {
        const float* xr = x + (size_t)row0 * NROW;
        #pragma unroll
        for (int p = 0; p < 4; p++) {
            int q = warp + 12 * p;
            if (q < NQUAD) {
                const float* b = xr + q * 256 + xoff;
                bfly8_store(__ldcs((const float4*)b), __ldcs((const float4*)(b + 32)),
                            sm + OFF_B0, 4 * q + g, tg, scale);
            }
        }
    }
    __syncthreads();

    int buf = 0;
    for (int row = row0; row < rows; row += stride) {
        const int nxt = row + stride;
        const bool have_nxt = nxt < rows;
        char* bnext = sm + (buf ? OFF_B0 : OFF_B1);

        // -- prefetch next row's quads (streaming loads, retire under GEMM) --
        float4 pfl[4], pfh[4];
        if (have_nxt) {
            const float* xn = x + (size_t)nxt * NROW;
            #pragma unroll
            for (int p = 0; p < 4; p++) {
                int q = warp + 12 * p;
                if (q < NQUAD) {
                    const float* b = xn + q * 256 + xoff;
                    pfl[p] = __ldcs((const float4*)b);
                    pfh[p] = __ldcs((const float4*)(b + 32));
                }
            }
        }

        // -------- GEMM row i: 32j x 32m per warp --------
        uint32_t bbase = sbase + (buf ? OFF_B1 : OFF_B0) + b_lane_off;
        float acc[2][4][4];
        #pragma unroll
        for (int jt2 = 0; jt2 < 2; jt2++)
            #pragma unroll
            for (int n = 0; n < 4; n++)
                acc[jt2][n][0] = acc[jt2][n][1] = acc[jt2][n][2] = acc[jt2][n][3] = 0.f;

        #pragma unroll
        for (int kt = 0; kt < 11; kt++) {
            uint32_t bk = bbase + (uint32_t)(kt * 16 * BSTR);
            uint32_t b0[4], b1[4];
            ldsm_x4t(b0, bk);
            ldsm_x4t(b1, bk + 32);
            #pragma unroll
            for (int jt2 = 0; jt2 < 2; jt2++) {
                mma_f16(acc[jt2][0], a_frag[jt2][kt], b0[0], b0[1]);
                mma_f16(acc[jt2][1], a_frag[jt2][kt], b0[2], b0[3]);
                mma_f16(acc[jt2][2], a_frag[jt2][kt], b1[0], b1[1]);
                mma_f16(acc[jt2][3], a_frag[jt2][kt], b1[2], b1[3]);
            }
        }

        // -------- epilogue: streaming stores (r10 addressing) --------
        {
            float* orow = out + (size_t)row * NROW + wm * 32 + eq * 2;
            #pragma unroll
            for (int jt2 = 0; jt2 < 2; jt2++) {
                int j1 = wj * 32 + jt2 * 16 + er;
                int j2 = j1 + 8;
                if (j1 < KDIM) {
                    float* o1 = orow + j1 * MDIM;
                    #pragma unroll
                    for (int n = 0; n < 4; n++)
                        __stcs((float2*)(o1 + n * 8), make_float2(acc[jt2][n][0], acc[jt2][n][1]));
                }
                if (j2 < KDIM) {
                    float* o2 = orow + j2 * MDIM;
                    #pragma unroll
                    for (int n = 0; n < 4; n++)
                        __stcs((float2*)(o2 + n * 8), make_float2(acc[jt2][n][2], acc[jt2][n][3]));
                }
            }
        }

        // -- butterfly next row from prefetched regs --
        if (have_nxt) {
            #pragma unroll
            for (int p = 0; p < 4; p++) {
                int q = warp + 12 * p;
                if (q < NQUAD)
                    bfly8_store(pfl[p], pfh[p], bnext, 4 * q + g, tg, scale);
            }
        }
        buf ^= 1;
        __syncthreads();
    }
}

extern "C" void kernel_launch(void* const* d_in, const int* in_sizes, int n_in,
                              void* d_out, int out_size) {
    const float* x   = (const float*)d_in[0];
    const float* had = (const float*)d_in[1];
    float* out = (float*)d_out;
    int rows = in_sizes[0] / NROW;

    cudaFuncSetAttribute(onl_had_r16_kernel,
                         cudaFuncAttributeMaxDynamicSharedMemorySize, SMEM_DYN);
    int grid = rows < 152 ? rows : 152;
    onl_had_r16_kernel<<<grid, NT, SMEM_DYN>>>(x, had, out, rows);
}